// round 17
// baseline (speedup 1.0000x reference)
#include <cuda_runtime.h>
#include <cuda_bf16.h>
#include <cstdint>

// Problem shape
#define BATCH 1024
#define HEADS 16
#define SEQ   8
#define DKDIM 32
#define NHEAD (BATCH * HEADS)            // 16384 heads
#define HEAD_ELEMS (SEQ * DKDIM)         // 256 floats per head tensor
#define CTX_ELEMS  (NHEAD * HEAD_ELEMS)  // 4194304

#define WARPS_PER_BLOCK 8
#define THREADS (WARPS_PER_BLOCK * 32)
#define ROWPAD 36   // K/V row stride: 144B, 16B-aligned, 4-bank skew/row -> conflict-free

__device__ __forceinline__ float warp8_sum(float v) {
    v += __shfl_xor_sync(0xFFFFFFFFu, v, 1);
    v += __shfl_xor_sync(0xFFFFFFFFu, v, 2);
    v += __shfl_xor_sync(0xFFFFFFFFu, v, 4);
    return v;
}
__device__ __forceinline__ float dot4(const float4 a, const float4 b) {
    return a.x*b.x + a.y*b.y + a.z*b.z + a.w*b.w;
}

// cp.async.cg 16B with L2 evict-first cache policy (single-use streaming data)
__device__ __forceinline__ void cp_async_cg_ef(void* smem_dst, const void* gmem_src,
                                               const uint64_t pol) {
    const uint32_t saddr = (uint32_t)__cvta_generic_to_shared(smem_dst);
    asm volatile(
        "cp.async.cg.shared.global.L2::cache_hint [%0], [%1], 16, %2;\n"
        :: "r"(saddr), "l"(gmem_src), "l"(pol) : "memory");
}

__global__ __launch_bounds__(THREADS, 6)
void sdpa_kernel(const float* __restrict__ Qg,
                 const float* __restrict__ Kg,
                 const float* __restrict__ Vg,
                 const int* __restrict__ Mg,   // bool mask materialized as int32
                 const float* __restrict__ Hg,
                 float* __restrict__ ctx_out,
                 float* __restrict__ w_out)
{
    __shared__ float sK[WARPS_PER_BLOCK][SEQ][ROWPAD];
    __shared__ float sV[WARPS_PER_BLOCK][SEQ][ROWPAD];
    __shared__ float sWf[WARPS_PER_BLOCK][64];      // flat weights

    const int w    = threadIdx.x >> 5;
    const int lane = threadIdx.x & 31;
    const int hid  = blockIdx.x * WARPS_PER_BLOCK + w;

    const float INV_SQRT_DK = 0.17677669529663687f;  // 1/sqrt(32)

    const int g = lane >> 3;          // q-row group 0..3
    const int c = lane & 7;           // chunk / k index 0..7

    // L2 evict-first policy for the K/V stream (lines are dead once in smem)
    uint64_t pol;
    asm volatile("createpolicy.fractional.L2::evict_first.b64 %0, 1.0;" : "=l"(pol));

    // ---- K/V staging via cp.async.cg + evict-first L2 hint ----
    const float4* K4 = (const float4*)(Kg + (size_t)hid * HEAD_ELEMS);
    const float4* V4 = (const float4*)(Vg + (size_t)hid * HEAD_ELEMS);
    #pragma unroll
    for (int t = lane; t < 64; t += 32) {
        const int row = t >> 3;
        const int c4  = t & 7;
        cp_async_cg_ef(&((float4*)&sK[w][row][0])[c4], &K4[t], pol);
        cp_async_cg_ef(&((float4*)&sV[w][row][0])[c4], &V4[t], pol);
    }
    asm volatile("cp.async.commit_group;" ::: "memory");

    // ---- overlap: streaming (evict-first) register loads while copies fly ----
    const int* mrow = Mg + (size_t)hid * 64;
    const int m0 = __ldcs(&mrow[lane]);        // mask[q=g][k=c]
    const int m1 = __ldcs(&mrow[lane + 32]);   // mask[q=g+4][k=c]

    // Q stays in registers: lane owns Q[g][chunk c] and Q[g+4][chunk c]
    const float4* Q4 = (const float4*)(Qg + (size_t)hid * HEAD_ELEMS);
    const float4 Qa = __ldcs(&Q4[lane]);
    const float4 Qb = __ldcs(&Q4[lane + 32]);

    asm volatile("cp.async.wait_group 0;" ::: "memory");
    __syncwarp();

    // ---- score partials: pa[k] = dot4(Q[g][c], K[k][c]) ----
    float pa[8], pb[8];
    #pragma unroll
    for (int k = 0; k < SEQ; k++) {
        const float4 kv = *((const float4*)&sK[w][k][0] + c);  // column read, bcast x4
        pa[k] = dot4(Qa, kv);
        pb[k] = dot4(Qb, kv);
    }

    // ---- recursive-halving reduce over the 8 chunk-lanes (same g) ----
    const bool h4 = (c & 4) != 0;
    const bool h2 = (c & 2) != 0;
    const bool h1 = (c & 1) != 0;

    float ra[4], rb[4];
    #pragma unroll
    for (int j = 0; j < 4; j++) {
        const float sendA = h4 ? pa[j] : pa[j + 4];
        const float keepA = h4 ? pa[j + 4] : pa[j];
        ra[j] = keepA + __shfl_xor_sync(0xFFFFFFFFu, sendA, 4);
        const float sendB = h4 ? pb[j] : pb[j + 4];
        const float keepB = h4 ? pb[j + 4] : pb[j];
        rb[j] = keepB + __shfl_xor_sync(0xFFFFFFFFu, sendB, 4);
    }
    float ta[2], tb[2];
    #pragma unroll
    for (int j = 0; j < 2; j++) {
        const float sendA = h2 ? ra[j] : ra[j + 2];
        const float keepA = h2 ? ra[j + 2] : ra[j];
        ta[j] = keepA + __shfl_xor_sync(0xFFFFFFFFu, sendA, 2);
        const float sendB = h2 ? rb[j] : rb[j + 2];
        const float keepB = h2 ? rb[j + 2] : rb[j];
        tb[j] = keepB + __shfl_xor_sync(0xFFFFFFFFu, sendB, 2);
    }
    float s0, s1;
    {
        const float sendA = h1 ? ta[0] : ta[1];
        const float keepA = h1 ? ta[1] : ta[0];
        s0 = keepA + __shfl_xor_sync(0xFFFFFFFFu, sendA, 1);
        const float sendB = h1 ? tb[0] : tb[1];
        const float keepB = h1 ? tb[1] : tb[0];
        s1 = keepB + __shfl_xor_sync(0xFFFFFFFFu, sendB, 1);
    }
    // lane holds s[g][c] and s[g+4][c]

    // hyper loads (streaming): consumed only in the epilogue; softmax + sWf
    // round-trip + context loop cover the latency.
    const float4* H4 = (const float4*)(Hg + (size_t)hid * HEAD_ELEMS);
    const float4 ha = __ldcs(&H4[lane]);
    const float4 hb = __ldcs(&H4[lane + 32]);

    // masked -> -60: exp(-60) ~ 8.8e-27 (== ref's exact 0 within tolerance);
    // all-masked row -> uniform 1/8, matching reference softmax of a constant
    // row. Unmasked |s| <~ 8 so no overflow without max-subtraction.
    s0 = m0 ? -60.0f : s0 * INV_SQRT_DK;
    s1 = m1 ? -60.0f : s1 * INV_SQRT_DK;

    // ---- softmax over k, no max pass ----
    const float e0 = __expf(s0);
    const float e1 = __expf(s1);
    const float w0 = __fdividef(e0, warp8_sum(e0));
    const float w1 = __fdividef(e1, warp8_sum(e1));

    // weights output: flat indices -> fully coalesced streaming stores
    float* wo = w_out + (size_t)hid * 64;
    __stcs(&wo[lane],      w0);
    __stcs(&wo[lane + 32], w1);

    sWf[w][lane]      = w0;
    sWf[w][lane + 32] = w1;
    __syncwarp();

    // ---- context: lane owns (row g, chunk c) and (row g+4, chunk c) ----
    const float4* wr0 = (const float4*)&sWf[w][g << 3];
    const float4* wr1 = (const float4*)&sWf[w][(g + 4) << 3];
    const float4 wa0 = wr0[0], wa1 = wr0[1];
    const float4 wb0 = wr1[0], wb1 = wr1[1];
    const float wreg0[8] = { wa0.x, wa0.y, wa0.z, wa0.w, wa1.x, wa1.y, wa1.z, wa1.w };
    const float wreg1[8] = { wb0.x, wb0.y, wb0.z, wb0.w, wb1.x, wb1.y, wb1.z, wb1.w };

    float4 acc0 = make_float4(0.f,0.f,0.f,0.f);
    float4 acc1 = make_float4(0.f,0.f,0.f,0.f);
    #pragma unroll
    for (int k = 0; k < SEQ; k++) {
        const float4 vv = ((const float4*)&sV[w][k][0])[c];   // one LDS feeds both rows
        acc0.x += wreg0[k]*vv.x; acc0.y += wreg0[k]*vv.y; acc0.z += wreg0[k]*vv.z; acc0.w += wreg0[k]*vv.w;
        acc1.x += wreg1[k]*vv.x; acc1.y += wreg1[k]*vv.y; acc1.z += wreg1[k]*vv.z; acc1.w += wreg1[k]*vv.w;
    }

    float4 oa, ob;
    oa.x = acc0.x*ha.x; oa.y = acc0.y*ha.y; oa.z = acc0.z*ha.z; oa.w = acc0.w*ha.w;
    ob.x = acc1.x*hb.x; ob.y = acc1.y*hb.y; ob.z = acc1.z*hb.z; ob.w = acc1.w*hb.w;
    float4* O4 = (float4*)(ctx_out + (size_t)hid * HEAD_ELEMS);
    __stcs(&O4[lane],      oa);
    __stcs(&O4[lane + 32], ob);
}

extern "C" void kernel_launch(void* const* d_in, const int* in_sizes, int n_in,
                              void* d_out, int out_size) {
    const float* Q  = (const float*)d_in[0];
    const float* K  = (const float*)d_in[1];
    const float* V  = (const float*)d_in[2];
    const int*   M  = (const int*)d_in[3];
    const float* Hy = (const float*)d_in[4];

    float* ctx = (float*)d_out;                 // [B,H,S,DK] flattened, first
    float* wts = ctx + CTX_ELEMS;               // [B,H,S,S] flattened, second

    const int blocks = NHEAD / WARPS_PER_BLOCK; // 2048
    sdpa_kernel<<<blocks, THREADS>>>(Q, K, V, M, Hy, ctx, wts);
}